// round 7
// baseline (speedup 1.0000x reference)
#include <cuda_runtime.h>
#include <cuda_fp16.h>

// Problem constants
#define DIM   96
#define NBIN  64
#define BSZ   15
#define NFLT  ((size_t)DIM*DIM*DIM*NBIN)   // 56,623,104 halves
#define WPV   32                            // half2 words per voxel (64 bins)

// stage-2 geometry: block = (y, x-quarter)
#define XOUT  24                            // output x per block
#define RSLOT (XOUT * WPV)                  // 768 words per ring slot
#define RING_WORDS (16 * RSLOT)             // 16-slot ring (2-row iterations)
#define RING_BYTES (RING_WORDS * 4)         // 49152 B dynamic smem

// 113 MB fp16 scratch (Ysum of binned volume), layout [z][y][x][bin]
__device__ __align__(16) __half g_h0[NFLT];

__device__ __forceinline__ unsigned pack2(float a, float b) {
    __half2 h = __float22half2_rn(make_float2(a, b));
    return *reinterpret_cast<unsigned*>(&h);
}
__device__ __forceinline__ float2 unpack2(unsigned u) {
    __half2 h = *reinterpret_cast<__half2*>(&u);
    return __half22float2(h);
}

// ---------------------------------------------------------------------------
// Stage 1: gradients -> soft binning (fp16 smem) -> Y sliding sum -> fp16
// One block (256 thr) per (z,x) line over y. Same structure as the proven
// binx kernel with x<->y roles swapped; output layout [z][y][x][bin].
// ---------------------------------------------------------------------------
#define VSTRH 66    // halves per y-row in smem (64 + 2 pad) = 33 words
__global__ void __launch_bounds__(256) binY_kernel(const float* __restrict__ x,
                                                   __half* __restrict__ V)
{
    __shared__ __align__(16) __half Vs[DIM * VSTRH];   // 12.4 KB
    unsigned* Vsu = reinterpret_cast<unsigned*>(Vs);   // 33 words per y-row

    const int tid  = threadIdx.x;
    const int line = blockIdx.x;          // 0..9215
    const int xi   = line % DIM;
    const int zi   = line / DIM;

    for (int i = tid; i < DIM * VSTRH / 2; i += 256) Vsu[i] = 0u;
    __syncthreads();

    if (tid < DIM) {
        const int yi = tid;
        const int v  = (zi * DIM + yi) * DIM + xi;

        const float xp = (xi < DIM - 1) ? x[v + 1]       : 0.f;
        const float xm = (xi > 0)       ? x[v - 1]       : 0.f;
        const float yp = (yi < DIM - 1) ? x[v + DIM]     : 0.f;
        const float ym = (yi > 0)       ? x[v - DIM]     : 0.f;
        const float zp = (zi < DIM - 1) ? x[v + DIM*DIM] : 0.f;
        const float zm = (zi > 0)       ? x[v - DIM*DIM] : 0.f;
        const float gx = xp - xm, gy = yp - ym, gz = zp - zm;

        const float EPS    = 2.2204460492503131e-16f;
        const float TWO_PI = (float)(2.0 * 3.14159265358979323846);
        const float PI_F   = (float)(3.14159265358979323846);
        const float TSTEP  = TWO_PI / 8.0f;
        const float PSTEP  = PI_F   / 8.0f;

        const float r   = sqrtf(gx*gx + gy*gy + gz*gz);
        float theta     = atanf(gy / (gx + EPS));
        const float phi = acosf(gz / (r + EPS));
        if (theta < 0.f) theta += TWO_PI;

        const float t_raw = theta / TSTEP;
        const float p_raw = phi   / PSTEP;

        const float ft = floorf(t_raw);
        int lt = (int)ft;            if (lt == 8) lt = 0;
        int lp = (int)floorf(p_raw); if (lp == 8) lp = 0;
        const int ht = (lt + 1) & 7;
        const int hp = (lp + 1) & 7;

        // theta frac intentionally reused for phi ratios (reference bug, faithful)
        const float frac  = t_raw - ft;
        const float w_lo  = fminf(frac, 1.0f - frac);
        const float w_hi  = 1.0f - w_lo;
        const float wp_lo = (frac == 0.0f) ? 1.0f : w_lo;
        const float wp_hi = 1.0f - wp_lo;

        // 4 target bins are provably distinct -> plain stores
        __half* row = &Vs[yi * VSTRH];
        row[lt*8 + lp] = __float2half_rn(r * w_lo * wp_lo);
        row[ht*8 + lp] = __float2half_rn(r * w_hi * wp_lo);
        row[lt*8 + hp] = __float2half_rn(r * w_lo * wp_hi);
        row[ht*8 + hp] = __float2half_rn(r * w_hi * wp_hi);
    }
    __syncthreads();

    // running Y-window: thread = (bin-word b, segment of 12 y)
    {
        const int b   = tid & 31;
        const int seg = tid >> 5;
        const int i0  = seg * 12;

        float w0 = 0.f, w1 = 0.f;
        #pragma unroll
        for (int j = 0; j < BSZ - 1; j++) {
            const int rr = i0 + j;
            if (rr < DIM) {
                const float2 a = unpack2(Vsu[rr * 33 + b]);
                w0 += a.x; w1 += a.y;
            }
        }

        unsigned* outu = reinterpret_cast<unsigned*>(V);
        #pragma unroll
        for (int i = i0; i < i0 + 12; i++) {
            const int hi = i + BSZ - 1;
            if (hi < DIM) {
                const float2 a = unpack2(Vsu[hi * 33 + b]);
                w0 += a.x; w1 += a.y;
            }
            // [z][y=i][x][bin] : 128B line per warp store
            outu[((zi * DIM + i) * DIM + xi) * WPV + b] = pack2(w0, w1);
            const float2 s = unpack2(Vsu[i * 33 + b]);
            w0 -= s.x; w1 -= s.y;
        }
    }
}

// ---------------------------------------------------------------------------
// Stage 2 (fused X+Z): block = (y, x-quarter). Per z-row: all 256 threads run
// a running X-window (fully coalesced 128B LDGs) into a 16-slot smem ring;
// then the Z-window in fp32 register accumulators streams fp32 output.
// 2 z-rows per iteration (halves barrier count; ring slot reuse lag = 16).
// ---------------------------------------------------------------------------
__global__ void __launch_bounds__(256) xz_kernel(const __half* __restrict__ H,
                                                 float* __restrict__ out)
{
    extern __shared__ __align__(16) unsigned ring[];   // 16 * RSLOT words

    const int tid = threadIdx.x;
    const int y   = blockIdx.x;          // 0..95
    const int x0  = blockIdx.y * XOUT;   // 0,24,48,72

    // B (X-window) mapping: 32 bin-words x 8 x-segments, 3 outputs each
    const int col = tid & 31;
    const int seg = tid >> 5;
    const int xo0 = x0 + seg * 3;

    const unsigned* Hu = reinterpret_cast<const unsigned*>(H);

    // C (Z-window) mapping: 768 units = 24 x * 32 words, 3 per thread
    float2 acc[3];
    int    rb[3];
    int    ob[3];
    #pragma unroll
    for (int k = 0; k < 3; k++) {
        const int u   = tid + k * 256;
        const int xl  = u >> 5;          // local x 0..23
        const int c   = u & 31;
        rb[k] = xl * WPV + c;
        ob[k] = ((y * DIM) + x0 + xl) * WPV + c;  // float2 offset (+ zp*96*96*32)
        acc[k] = make_float2(0.f, 0.f);
    }

    for (int t = 0; t < DIM / 2; t++) {
        // ---- B: X-window for rows z=2t, 2t+1 -> ring ----
        #pragma unroll
        for (int dz = 0; dz < 2; dz++) {
            const int z = 2 * t + dz;
            const unsigned* p = Hu + ((z * DIM + y) * DIM) * WPV + col;
            float w0 = 0.f, w1 = 0.f;
            #pragma unroll
            for (int j = 0; j < BSZ - 1; j++) {
                const int xx = xo0 + j;
                if (xx < DIM) {
                    const float2 a = unpack2(p[xx * WPV]);
                    w0 += a.x; w1 += a.y;
                }
            }
            unsigned* slot = ring + (z & 15) * RSLOT;
            #pragma unroll
            for (int i = 0; i < 3; i++) {
                const int xo = xo0 + i;
                const int xl = xo + BSZ - 1;
                if (xl < DIM) {
                    const float2 a = unpack2(p[xl * WPV]);
                    w0 += a.x; w1 += a.y;
                }
                slot[(xo - x0) * WPV + col] = pack2(w0, w1);
                const float2 s = unpack2(p[xo * WPV]);
                w0 -= s.x; w1 -= s.y;
            }
        }
        __syncthreads();

        // ---- C: Z running window ----
        #pragma unroll
        for (int dz = 0; dz < 2; dz++) {
            const int z = 2 * t + dz;
            const unsigned* snew = ring + (z & 15) * RSLOT;
            #pragma unroll
            for (int k = 0; k < 3; k++) {
                const float2 a = unpack2(snew[rb[k]]);
                acc[k].x += a.x; acc[k].y += a.y;
            }
            if (z >= BSZ - 1) {
                const int zp = z - (BSZ - 1);
                const unsigned* sold = ring + (zp & 15) * RSLOT;
                float2* op = reinterpret_cast<float2*>(out) + (size_t)zp * (DIM * DIM * WPV);
                #pragma unroll
                for (int k = 0; k < 3; k++) {
                    __stcs(op + ob[k], acc[k]);
                    const float2 s = unpack2(sold[rb[k]]);
                    acc[k].x -= s.x; acc[k].y -= s.y;
                }
            }
        }
        __syncthreads();
    }

    // ---- tail: zp = 82..95 (window clamps past the end); slots still intact ----
    for (int zp = DIM - BSZ + 1; zp < DIM; zp++) {
        const unsigned* sold = ring + (zp & 15) * RSLOT;
        float2* op = reinterpret_cast<float2*>(out) + (size_t)zp * (DIM * DIM * WPV);
        #pragma unroll
        for (int k = 0; k < 3; k++) {
            __stcs(op + ob[k], acc[k]);
            const float2 s = unpack2(sold[rb[k]]);
            acc[k].x -= s.x; acc[k].y -= s.y;
        }
    }
}

// ---------------------------------------------------------------------------
extern "C" void kernel_launch(void* const* d_in, const int* in_sizes, int n_in,
                              void* d_out, int out_size)
{
    const float* x = (const float*)d_in[0];

    void* p0 = nullptr;
    cudaGetSymbolAddress(&p0, g_h0);

    cudaFuncSetAttribute(xz_kernel, cudaFuncAttributeMaxDynamicSharedMemorySize,
                         RING_BYTES);

    binY_kernel<<<DIM * DIM, 256>>>(x, (__half*)p0);        // x -> Ysum (fp16)

    dim3 g(DIM, 4);                                          // (y, x-quarter)
    xz_kernel<<<g, 256, RING_BYTES>>>((const __half*)p0, (float*)d_out);
}

// round 8
// speedup vs baseline: 1.1217x; 1.1217x over previous
#include <cuda_runtime.h>
#include <cuda_fp16.h>

// Problem constants
#define DIM   96
#define NBIN  64              // 8 theta * 8 phi
#define BSZ   15              // sliding window
#define NVOX  (DIM*DIM*DIM)               // 884736
#define NFLT  ((size_t)NVOX * NBIN)       // 56,623,104
#define LINEH (DIM * NBIN)                // halves per (z,y) line = 6144
#define LINEU2  (DIM * NBIN / 4)          // uint2 per y-row = 1536
#define PLANEU2 (DIM * LINEU2)            // 147456
#define VSTR  66                          // padded smem row stride (floats, even)

// two 113 MB fp16 scratch buffers (static device allocation — allowed)
__device__ __align__(16) __half g_h0[NFLT];
__device__ __align__(16) __half g_h1[NFLT];

__device__ __forceinline__ unsigned pack2(float a, float b) {
    __half2 h = __float22half2_rn(make_float2(a, b));
    return *reinterpret_cast<unsigned*>(&h);
}
__device__ __forceinline__ float2 unpack2(unsigned u) {
    __half2 h = *reinterpret_cast<__half2*>(&u);
    return __half22float2(h);
}

// ---------------------------------------------------------------------------
// Stage 1 (fused): gradients -> soft binning -> X sliding-window sum -> fp16
// One block (256 thr) per (z,y) line. Dense 96x64 histogram in smem; window
// sums via running accumulators, 8-way segmented along x, 2 bins per thread.
// Output written with DEFAULT policy: it must stay in L2 for slideY's reads.
// ---------------------------------------------------------------------------
__global__ void __launch_bounds__(256) binx_kernel(const float* __restrict__ x,
                                                   __half* __restrict__ V)
{
    __shared__ float Vs[DIM * VSTR];      // 24.75 KB (padded rows)

    const int tid  = threadIdx.x;
    const int line = blockIdx.x;          // 0..9215
    const int yi   = line % DIM;
    const int zi   = line / DIM;

    for (int i = tid; i < DIM * VSTR; i += 256) Vs[i] = 0.f;
    __syncthreads();

    if (tid < DIM) {
        const int xi = tid;
        const int v  = (zi * DIM + yi) * DIM + xi;

        const float xp = (xi < DIM - 1) ? x[v + 1]       : 0.f;
        const float xm = (xi > 0)       ? x[v - 1]       : 0.f;
        const float yp = (yi < DIM - 1) ? x[v + DIM]     : 0.f;
        const float ym = (yi > 0)       ? x[v - DIM]     : 0.f;
        const float zp = (zi < DIM - 1) ? x[v + DIM*DIM] : 0.f;
        const float zm = (zi > 0)       ? x[v - DIM*DIM] : 0.f;
        const float gx = xp - xm, gy = yp - ym, gz = zp - zm;

        const float EPS    = 2.2204460492503131e-16f;
        const float TWO_PI = (float)(2.0 * 3.14159265358979323846);
        const float PI_F   = (float)(3.14159265358979323846);
        const float TSTEP  = TWO_PI / 8.0f;
        const float PSTEP  = PI_F   / 8.0f;

        const float r   = sqrtf(gx*gx + gy*gy + gz*gz);
        float theta     = atanf(gy / (gx + EPS));
        const float phi = acosf(gz / (r + EPS));
        if (theta < 0.f) theta += TWO_PI;

        const float t_raw = theta / TSTEP;
        const float p_raw = phi   / PSTEP;

        const float ft = floorf(t_raw);
        int lt = (int)ft;            if (lt == 8) lt = 0;
        int lp = (int)floorf(p_raw); if (lp == 8) lp = 0;
        const int ht = (lt + 1) & 7;
        const int hp = (lp + 1) & 7;

        // theta frac intentionally reused for phi ratios (reference bug, faithful)
        const float frac  = t_raw - ft;
        const float w_lo  = fminf(frac, 1.0f - frac);
        const float w_hi  = 1.0f - w_lo;
        const float wp_lo = (frac == 0.0f) ? 1.0f : w_lo;
        const float wp_hi = 1.0f - wp_lo;

        float* row = &Vs[xi * VSTR];          // row exclusive to this thread
        row[lt*8 + lp] += r * w_lo * wp_lo;
        row[ht*8 + lp] += r * w_hi * wp_lo;
        row[lt*8 + hp] += r * w_lo * wp_hi;
        row[ht*8 + hp] += r * w_hi * wp_hi;
    }
    __syncthreads();

    // running X-window: thread = (bin-pair b, segment seg of 12 x)
    {
        const int b   = tid & 31;
        const int seg = tid >> 5;
        const int i0  = seg * 12;

        float w0 = 0.f, w1 = 0.f;
        #pragma unroll
        for (int j = 0; j < BSZ - 1; j++) {
            const int rr = i0 + j;
            if (rr < DIM) {
                const float2 a = *reinterpret_cast<const float2*>(&Vs[rr * VSTR + 2*b]);
                w0 += a.x; w1 += a.y;
            }
        }

        unsigned* outu = reinterpret_cast<unsigned*>(V + (size_t)line * LINEH);
        #pragma unroll
        for (int i = i0; i < i0 + 12; i++) {
            const int hi = i + BSZ - 1;
            if (hi < DIM) {
                const float2 a = *reinterpret_cast<const float2*>(&Vs[hi * VSTR + 2*b]);
                w0 += a.x; w1 += a.y;
            }
            outu[i * 32 + b] = pack2(w0, w1);          // default: keep in L2
            const float2 s = *reinterpret_cast<const float2*>(&Vs[i * VSTR + 2*b]);
            w0 -= s.x; w1 -= s.y;
        }
    }
}

// ---------------------------------------------------------------------------
// Stage 2: sliding sum along Y, fp16 -> fp16. One thread per (z,x,q4) column.
// Reads evict-first (__ldcs) so they don't evict binx's L2-resident output;
// writes DEFAULT so slideZ finds them in L2.
// ---------------------------------------------------------------------------
__global__ void __launch_bounds__(256) slideY_kernel(const uint2* __restrict__ in,
                                                     uint2* __restrict__ out)
{
    const int t = blockIdx.x * 256 + threadIdx.x;   // < 96*96*16 (grid exact)
    const int q = t & 15;
    const int c = t >> 4;
    const int xi = c % DIM, zi = c / DIM;
    const int base   = zi * PLANEU2 + xi * 16 + q;
    const int stride = LINEU2;

    float s0 = 0.f, s1 = 0.f, s2 = 0.f, s3 = 0.f;
    #pragma unroll
    for (int j = 0; j < BSZ - 1; j++) {
        const uint2 u = __ldcs(&in[base + j * stride]);
        const float2 a = unpack2(u.x), b = unpack2(u.y);
        s0 += a.x; s1 += a.y; s2 += b.x; s3 += b.y;
    }

    int off = base;
    #pragma unroll 4
    for (int i = 0; i < DIM; i++) {
        if (i + BSZ - 1 < DIM) {
            const uint2 u = __ldcs(&in[base + (i + BSZ - 1) * stride]);
            const float2 a = unpack2(u.x), b = unpack2(u.y);
            s0 += a.x; s1 += a.y; s2 += b.x; s3 += b.y;
        }
        uint2 o; o.x = pack2(s0, s1); o.y = pack2(s2, s3);
        out[off] = o;                                // default: keep in L2
        const uint2 u = __ldcs(&in[off]);            // trailing (L1/L2 hit)
        const float2 a = unpack2(u.x), b = unpack2(u.y);
        s0 -= a.x; s1 -= a.y; s2 -= b.x; s3 -= b.y;
        off += stride;
    }
}

// ---------------------------------------------------------------------------
// Stage 3: sliding sum along Z, fp16 -> fp32 (d_out). One thread per (y,x,q4).
// Reads evict-first (should hit L2 from slideY); writes streaming (final).
// ---------------------------------------------------------------------------
__global__ void __launch_bounds__(256) slideZ_kernel(const uint2* __restrict__ in,
                                                     float4* __restrict__ out)
{
    const int t = blockIdx.x * 256 + threadIdx.x;   // < 96*96*16
    const int q = t & 15;
    const int c = t >> 4;
    const int xi = c % DIM, yi = c / DIM;
    const int base   = yi * LINEU2 + xi * 16 + q;
    const int stride = PLANEU2;

    float s0 = 0.f, s1 = 0.f, s2 = 0.f, s3 = 0.f;
    #pragma unroll
    for (int j = 0; j < BSZ - 1; j++) {
        const uint2 u = __ldcs(&in[base + j * stride]);
        const float2 a = unpack2(u.x), b = unpack2(u.y);
        s0 += a.x; s1 += a.y; s2 += b.x; s3 += b.y;
    }

    int off = base;
    #pragma unroll 4
    for (int i = 0; i < DIM; i++) {
        if (i + BSZ - 1 < DIM) {
            const uint2 u = __ldcs(&in[base + (i + BSZ - 1) * stride]);
            const float2 a = unpack2(u.x), b = unpack2(u.y);
            s0 += a.x; s1 += a.y; s2 += b.x; s3 += b.y;
        }
        __stcs(&out[((i * DIM + yi) * DIM + xi) * 16 + q],
               make_float4(s0, s1, s2, s3));
        const uint2 u = __ldcs(&in[off]);            // trailing (L2 hit)
        const float2 a = unpack2(u.x), b = unpack2(u.y);
        s0 -= a.x; s1 -= a.y; s2 -= b.x; s3 -= b.y;
        off += stride;
    }
}

// ---------------------------------------------------------------------------
extern "C" void kernel_launch(void* const* d_in, const int* in_sizes, int n_in,
                              void* d_out, int out_size)
{
    const float* x = (const float*)d_in[0];

    void *p0 = nullptr, *p1 = nullptr;
    cudaGetSymbolAddress(&p0, g_h0);
    cudaGetSymbolAddress(&p1, g_h1);

    const int binBlocks   = DIM * DIM;                   // 9216 lines
    const int slideBlocks = (DIM * DIM * 16) / 256;      // 576

    binx_kernel<<<binBlocks, 256>>>(x, (__half*)p0);                         // x -> Xsum(h0)
    slideY_kernel<<<slideBlocks, 256>>>((const uint2*)p0, (uint2*)p1);       // h0 -> h1
    slideZ_kernel<<<slideBlocks, 256>>>((const uint2*)p1, (float4*)d_out);   // h1 -> out
}

// round 10
// speedup vs baseline: 1.6146x; 1.4394x over previous
#include <cuda_runtime.h>
#include <cuda_fp16.h>

// Problem constants
#define DIM   96
#define NBIN  64              // 8 theta * 8 phi
#define BSZ   15              // sliding window
#define NVOX  (DIM*DIM*DIM)               // 884736
#define NFLT  ((size_t)NVOX * NBIN)       // 56,623,104
#define LINEH (DIM * NBIN)                // halves per (z,y) line = 6144
#define LINEU2  (DIM * NBIN / 4)          // uint2 per y-row = 1536
#define PLANEU2 (DIM * LINEU2)            // 147456

// two 113 MB fp16 scratch buffers (static device allocation — allowed)
__device__ __align__(16) __half g_h0[NFLT];
__device__ __align__(16) __half g_h1[NFLT];

__device__ __forceinline__ unsigned pack2(float a, float b) {
    __half2 h = __float22half2_rn(make_float2(a, b));
    return *reinterpret_cast<unsigned*>(&h);
}
__device__ __forceinline__ float2 unpack2(unsigned u) {
    __half2 h = *reinterpret_cast<__half2*>(&u);
    return __half22float2(h);
}

// ---------------------------------------------------------------------------
// Stage 1: gradients -> soft binning (fp16 smem) -> X sliding sum -> fp16
// One block (256 thr) per (z,y) line. fp16 histogram halves smem traffic.
// ---------------------------------------------------------------------------
#define VSTRH 66    // halves per x-row in smem (64 + 2 pad) = 33 words
__global__ void __launch_bounds__(256) binx_kernel(const float* __restrict__ x,
                                                   __half* __restrict__ V)
{
    __shared__ __align__(16) __half Vs[DIM * VSTRH];   // 12.4 KB
    unsigned* Vsu = reinterpret_cast<unsigned*>(Vs);   // 33 words per x-row

    const int tid  = threadIdx.x;
    const int line = blockIdx.x;          // 0..9215
    const int yi   = line % DIM;
    const int zi   = line / DIM;

    // zero histogram (uint4 = 8 halves per store)
    {
        uint4* z4 = reinterpret_cast<uint4*>(Vs);
        const uint4 zz = make_uint4(0u, 0u, 0u, 0u);
        for (int i = tid; i < DIM * VSTRH / 8; i += 256) z4[i] = zz;
    }
    __syncthreads();

    if (tid < DIM) {
        const int xi = tid;
        const int v  = (zi * DIM + yi) * DIM + xi;

        const float xp = (xi < DIM - 1) ? x[v + 1]       : 0.f;
        const float xm = (xi > 0)       ? x[v - 1]       : 0.f;
        const float yp = (yi < DIM - 1) ? x[v + DIM]     : 0.f;
        const float ym = (yi > 0)       ? x[v - DIM]     : 0.f;
        const float zp = (zi < DIM - 1) ? x[v + DIM*DIM] : 0.f;
        const float zm = (zi > 0)       ? x[v - DIM*DIM] : 0.f;
        const float gx = xp - xm, gy = yp - ym, gz = zp - zm;

        const float EPS    = 2.2204460492503131e-16f;
        const float TWO_PI = (float)(2.0 * 3.14159265358979323846);
        const float PI_F   = (float)(3.14159265358979323846);
        const float TSTEP  = TWO_PI / 8.0f;
        const float PSTEP  = PI_F   / 8.0f;

        const float r   = sqrtf(gx*gx + gy*gy + gz*gz);
        float theta     = atanf(gy / (gx + EPS));
        const float phi = acosf(gz / (r + EPS));
        if (theta < 0.f) theta += TWO_PI;

        const float t_raw = theta / TSTEP;
        const float p_raw = phi   / PSTEP;

        const float ft = floorf(t_raw);
        int lt = (int)ft;            if (lt == 8) lt = 0;
        int lp = (int)floorf(p_raw); if (lp == 8) lp = 0;
        const int ht = (lt + 1) & 7;
        const int hp = (lp + 1) & 7;

        // theta frac intentionally reused for phi ratios (reference bug, faithful)
        const float frac  = t_raw - ft;
        const float w_lo  = fminf(frac, 1.0f - frac);
        const float w_hi  = 1.0f - w_lo;
        const float wp_lo = (frac == 0.0f) ? 1.0f : w_lo;
        const float wp_hi = 1.0f - wp_lo;

        // 4 target bins are provably distinct -> plain fp16 stores
        __half* row = &Vs[xi * VSTRH];
        row[lt*8 + lp] = __float2half_rn(r * w_lo * wp_lo);
        row[ht*8 + lp] = __float2half_rn(r * w_hi * wp_lo);
        row[lt*8 + hp] = __float2half_rn(r * w_lo * wp_hi);
        row[ht*8 + hp] = __float2half_rn(r * w_hi * wp_hi);
    }
    __syncthreads();

    // running X-window: thread = (bin-word b, segment seg of 12 x)
    {
        const int b   = tid & 31;
        const int seg = tid >> 5;
        const int i0  = seg * 12;

        float w0 = 0.f, w1 = 0.f;
        #pragma unroll
        for (int j = 0; j < BSZ - 1; j++) {
            const int rr = i0 + j;
            if (rr < DIM) {
                const float2 a = unpack2(Vsu[rr * 33 + b]);
                w0 += a.x; w1 += a.y;
            }
        }

        unsigned* outu = reinterpret_cast<unsigned*>(V + (size_t)line * LINEH);
        #pragma unroll
        for (int i = i0; i < i0 + 12; i++) {
            const int hi = i + BSZ - 1;
            if (hi < DIM) {
                const float2 a = unpack2(Vsu[hi * 33 + b]);
                w0 += a.x; w1 += a.y;
            }
            outu[i * 32 + b] = pack2(w0, w1);          // coalesced 128B/warp
            const float2 s = unpack2(Vsu[i * 33 + b]);
            w0 -= s.x; w1 -= s.y;
        }
    }
}

// ---------------------------------------------------------------------------
// Stage 2: sliding sum along Y, fp16 -> fp16. One thread per (z,x,q4) column.
// (exact R3 form — measured at DRAM roofline)
// ---------------------------------------------------------------------------
__global__ void __launch_bounds__(256) slideY_kernel(const uint2* __restrict__ in,
                                                     uint2* __restrict__ out)
{
    const int t = blockIdx.x * 256 + threadIdx.x;   // < 96*96*16 (grid exact)
    const int q = t & 15;
    const int c = t >> 4;
    const int xi = c % DIM, zi = c / DIM;
    const int base   = zi * PLANEU2 + xi * 16 + q;
    const int stride = LINEU2;

    float s0 = 0.f, s1 = 0.f, s2 = 0.f, s3 = 0.f;
    #pragma unroll
    for (int j = 0; j < BSZ - 1; j++) {
        const uint2 u = in[base + j * stride];
        const float2 a = unpack2(u.x), b = unpack2(u.y);
        s0 += a.x; s1 += a.y; s2 += b.x; s3 += b.y;
    }

    int off = base;
    #pragma unroll 4
    for (int i = 0; i < DIM; i++) {
        if (i + BSZ - 1 < DIM) {
            const uint2 u = in[base + (i + BSZ - 1) * stride];
            const float2 a = unpack2(u.x), b = unpack2(u.y);
            s0 += a.x; s1 += a.y; s2 += b.x; s3 += b.y;
        }
        uint2 o; o.x = pack2(s0, s1); o.y = pack2(s2, s3);
        __stcs(&out[off], o);
        const uint2 u = in[off];                    // trailing (cache hit)
        const float2 a = unpack2(u.x), b = unpack2(u.y);
        s0 -= a.x; s1 -= a.y; s2 -= b.x; s3 -= b.y;
        off += stride;
    }
}

// ---------------------------------------------------------------------------
// Stage 3: sliding sum along Z, fp16 -> fp32 (d_out). One thread per (y,x,q4).
// (exact R3 form)
// ---------------------------------------------------------------------------
__global__ void __launch_bounds__(256) slideZ_kernel(const uint2* __restrict__ in,
                                                     float4* __restrict__ out)
{
    const int t = blockIdx.x * 256 + threadIdx.x;   // < 96*96*16
    const int q = t & 15;
    const int c = t >> 4;
    const int xi = c % DIM, yi = c / DIM;
    const int base   = yi * LINEU2 + xi * 16 + q;
    const int stride = PLANEU2;

    float s0 = 0.f, s1 = 0.f, s2 = 0.f, s3 = 0.f;
    #pragma unroll
    for (int j = 0; j < BSZ - 1; j++) {
        const uint2 u = in[base + j * stride];
        const float2 a = unpack2(u.x), b = unpack2(u.y);
        s0 += a.x; s1 += a.y; s2 += b.x; s3 += b.y;
    }

    int off = base;
    #pragma unroll 4
    for (int i = 0; i < DIM; i++) {
        if (i + BSZ - 1 < DIM) {
            const uint2 u = in[base + (i + BSZ - 1) * stride];
            const float2 a = unpack2(u.x), b = unpack2(u.y);
            s0 += a.x; s1 += a.y; s2 += b.x; s3 += b.y;
        }
        __stcs(&out[((i * DIM + yi) * DIM + xi) * 16 + q],
               make_float4(s0, s1, s2, s3));
        const uint2 u = in[off];                    // trailing (cache hit)
        const float2 a = unpack2(u.x), b = unpack2(u.y);
        s0 -= a.x; s1 -= a.y; s2 -= b.x; s3 -= b.y;
        off += stride;
    }
}

// ---------------------------------------------------------------------------
extern "C" void kernel_launch(void* const* d_in, const int* in_sizes, int n_in,
                              void* d_out, int out_size)
{
    const float* x = (const float*)d_in[0];

    void *p0 = nullptr, *p1 = nullptr;
    cudaGetSymbolAddress(&p0, g_h0);
    cudaGetSymbolAddress(&p1, g_h1);

    const int binBlocks   = DIM * DIM;                   // 9216 lines
    const int slideBlocks = (DIM * DIM * 16) / 256;      // 576

    binx_kernel<<<binBlocks, 256>>>(x, (__half*)p0);                         // x -> Xsum(h0)
    slideY_kernel<<<slideBlocks, 256>>>((const uint2*)p0, (uint2*)p1);       // h0 -> h1
    slideZ_kernel<<<slideBlocks, 256>>>((const uint2*)p1, (float4*)d_out);   // h1 -> out
}

// round 11
// speedup vs baseline: 1.7785x; 1.1015x over previous
#include <cuda_runtime.h>
#include <cuda_fp16.h>

// Problem constants
#define DIM   96
#define NBIN  64              // 8 theta * 8 phi
#define BSZ   15              // sliding window
#define NVOX  (DIM*DIM*DIM)               // 884736
#define NFLT  ((size_t)NVOX * NBIN)       // 56,623,104
#define LINEH2 (DIM * NBIN / 2)           // half2 per (z,y) line = 3072
#define LINEU2  (DIM * NBIN / 4)          // uint2 per y-row = 1536
#define PLANEU2 (DIM * LINEU2)            // 147456
#define VSTR2 33                          // half2 per x-row in smem (odd -> conflict-free)

// two 113 MB fp16 scratch buffers (static device allocation — allowed)
__device__ __align__(16) __half g_h0[NFLT];
__device__ __align__(16) __half g_h1[NFLT];

__device__ __forceinline__ unsigned pack2(float a, float b) {
    __half2 h = __float22half2_rn(make_float2(a, b));
    return *reinterpret_cast<unsigned*>(&h);
}
__device__ __forceinline__ float2 unpack2(unsigned u) {
    __half2 h = *reinterpret_cast<__half2*>(&u);
    return __half22float2(h);
}

// ---------------------------------------------------------------------------
// Stage 1: gradients -> soft binning (fp16 smem) -> X sliding sum (half2) -> fp16
// One block (256 thr) per TWO (z,y) lines. Binning: 192 threads active.
// Window: thread = (line, bin-word, segment of 24 x), half2 running sums.
// ---------------------------------------------------------------------------
__global__ void __launch_bounds__(256) binx_kernel(const float* __restrict__ x,
                                                   __half* __restrict__ V)
{
    __shared__ __align__(16) __half2 Vs2[2 * DIM * VSTR2];   // 24.75 KB

    const int tid   = threadIdx.x;
    const int line0 = blockIdx.x * 2;     // lines line0, line0+1 (same z, adjacent y)

    // zero histograms (uint4 = 4 half2 per store)
    {
        uint4* z4 = reinterpret_cast<uint4*>(Vs2);
        const uint4 zz = make_uint4(0u, 0u, 0u, 0u);
        #pragma unroll
        for (int i = tid; i < 2 * DIM * VSTR2 / 4; i += 256) z4[i] = zz;
    }
    __syncthreads();

    if (tid < 2 * DIM) {
        const int l    = tid / DIM;       // which of the 2 lines
        const int xi   = tid % DIM;
        const int line = line0 + l;
        const int yi   = line % DIM;
        const int zi   = line / DIM;
        const int v    = (zi * DIM + yi) * DIM + xi;

        const float xp = (xi < DIM - 1) ? x[v + 1]       : 0.f;
        const float xm = (xi > 0)       ? x[v - 1]       : 0.f;
        const float yp = (yi < DIM - 1) ? x[v + DIM]     : 0.f;
        const float ym = (yi > 0)       ? x[v - DIM]     : 0.f;
        const float zp = (zi < DIM - 1) ? x[v + DIM*DIM] : 0.f;
        const float zm = (zi > 0)       ? x[v - DIM*DIM] : 0.f;
        const float gx = xp - xm, gy = yp - ym, gz = zp - zm;

        const float EPS    = 2.2204460492503131e-16f;
        const float TWO_PI = (float)(2.0 * 3.14159265358979323846);
        const float PI_F   = (float)(3.14159265358979323846);
        const float TSTEP  = TWO_PI / 8.0f;
        const float PSTEP  = PI_F   / 8.0f;

        const float r   = sqrtf(gx*gx + gy*gy + gz*gz);
        float theta     = atanf(gy / (gx + EPS));
        const float phi = acosf(gz / (r + EPS));
        if (theta < 0.f) theta += TWO_PI;

        const float t_raw = theta / TSTEP;
        const float p_raw = phi   / PSTEP;

        const float ft = floorf(t_raw);
        int lt = (int)ft;            if (lt == 8) lt = 0;
        int lp = (int)floorf(p_raw); if (lp == 8) lp = 0;
        const int ht = (lt + 1) & 7;
        const int hp = (lp + 1) & 7;

        // theta frac intentionally reused for phi ratios (reference bug, faithful)
        const float frac  = t_raw - ft;
        const float w_lo  = fminf(frac, 1.0f - frac);
        const float w_hi  = 1.0f - w_lo;
        const float wp_lo = (frac == 0.0f) ? 1.0f : w_lo;
        const float wp_hi = 1.0f - wp_lo;

        // 4 target bins are provably distinct -> plain fp16 stores
        __half* row = reinterpret_cast<__half*>(Vs2) + (l * DIM + xi) * (2 * VSTR2);
        row[lt*8 + lp] = __float2half_rn(r * w_lo * wp_lo);
        row[ht*8 + lp] = __float2half_rn(r * w_hi * wp_lo);
        row[lt*8 + hp] = __float2half_rn(r * w_lo * wp_hi);
        row[ht*8 + hp] = __float2half_rn(r * w_hi * wp_hi);
    }
    __syncthreads();

    // running X-window in half2: thread = (line l, bin-word b, segment of 24 x)
    {
        const int l   = tid >> 7;         // 0..1
        const int u   = tid & 127;
        const int b   = u & 31;           // half2 word within the 64-bin row
        const int seg = u >> 5;           // 0..3
        const int i0  = seg * 24;

        const __half2* row = Vs2 + l * (DIM * VSTR2);

        __half2 w = __float2half2_rn(0.f);
        #pragma unroll
        for (int j = 0; j < BSZ - 1; j++) {       // rows i0..i0+13 (max 85 < 96)
            w = __hadd2(w, row[(i0 + j) * VSTR2 + b]);
        }

        __half2* outv = reinterpret_cast<__half2*>(V) + (size_t)(line0 + l) * LINEH2;
        #pragma unroll
        for (int i = i0; i < i0 + 24; i++) {
            const int hi = i + BSZ - 1;
            if (hi < DIM) w = __hadd2(w, row[hi * VSTR2 + b]);
            outv[i * 32 + b] = w;                 // coalesced 128B/warp
            w = __hsub2(w, row[i * VSTR2 + b]);
        }
    }
}

// ---------------------------------------------------------------------------
// Stage 2: sliding sum along Y, fp16 -> fp16. One thread per (z,x,q4) column.
// (exact R3 form — measured at DRAM roofline)
// ---------------------------------------------------------------------------
__global__ void __launch_bounds__(256) slideY_kernel(const uint2* __restrict__ in,
                                                     uint2* __restrict__ out)
{
    const int t = blockIdx.x * 256 + threadIdx.x;   // < 96*96*16 (grid exact)
    const int q = t & 15;
    const int c = t >> 4;
    const int xi = c % DIM, zi = c / DIM;
    const int base   = zi * PLANEU2 + xi * 16 + q;
    const int stride = LINEU2;

    float s0 = 0.f, s1 = 0.f, s2 = 0.f, s3 = 0.f;
    #pragma unroll
    for (int j = 0; j < BSZ - 1; j++) {
        const uint2 u = in[base + j * stride];
        const float2 a = unpack2(u.x), b = unpack2(u.y);
        s0 += a.x; s1 += a.y; s2 += b.x; s3 += b.y;
    }

    int off = base;
    #pragma unroll 4
    for (int i = 0; i < DIM; i++) {
        if (i + BSZ - 1 < DIM) {
            const uint2 u = in[base + (i + BSZ - 1) * stride];
            const float2 a = unpack2(u.x), b = unpack2(u.y);
            s0 += a.x; s1 += a.y; s2 += b.x; s3 += b.y;
        }
        uint2 o; o.x = pack2(s0, s1); o.y = pack2(s2, s3);
        __stcs(&out[off], o);
        const uint2 u = in[off];                    // trailing (cache hit)
        const float2 a = unpack2(u.x), b = unpack2(u.y);
        s0 -= a.x; s1 -= a.y; s2 -= b.x; s3 -= b.y;
        off += stride;
    }
}

// ---------------------------------------------------------------------------
// Stage 3: sliding sum along Z, fp16 -> fp32 (d_out). One thread per (y,x,q4).
// (exact R3 form)
// ---------------------------------------------------------------------------
__global__ void __launch_bounds__(256) slideZ_kernel(const uint2* __restrict__ in,
                                                     float4* __restrict__ out)
{
    const int t = blockIdx.x * 256 + threadIdx.x;   // < 96*96*16
    const int q = t & 15;
    const int c = t >> 4;
    const int xi = c % DIM, yi = c / DIM;
    const int base   = yi * LINEU2 + xi * 16 + q;
    const int stride = PLANEU2;

    float s0 = 0.f, s1 = 0.f, s2 = 0.f, s3 = 0.f;
    #pragma unroll
    for (int j = 0; j < BSZ - 1; j++) {
        const uint2 u = in[base + j * stride];
        const float2 a = unpack2(u.x), b = unpack2(u.y);
        s0 += a.x; s1 += a.y; s2 += b.x; s3 += b.y;
    }

    int off = base;
    #pragma unroll 4
    for (int i = 0; i < DIM; i++) {
        if (i + BSZ - 1 < DIM) {
            const uint2 u = in[base + (i + BSZ - 1) * stride];
            const float2 a = unpack2(u.x), b = unpack2(u.y);
            s0 += a.x; s1 += a.y; s2 += b.x; s3 += b.y;
        }
        __stcs(&out[((i * DIM + yi) * DIM + xi) * 16 + q],
               make_float4(s0, s1, s2, s3));
        const uint2 u = in[off];                    // trailing (cache hit)
        const float2 a = unpack2(u.x), b = unpack2(u.y);
        s0 -= a.x; s1 -= a.y; s2 -= b.x; s3 -= b.y;
        off += stride;
    }
}

// ---------------------------------------------------------------------------
extern "C" void kernel_launch(void* const* d_in, const int* in_sizes, int n_in,
                              void* d_out, int out_size)
{
    const float* x = (const float*)d_in[0];

    void *p0 = nullptr, *p1 = nullptr;
    cudaGetSymbolAddress(&p0, g_h0);
    cudaGetSymbolAddress(&p1, g_h1);

    const int binBlocks   = DIM * DIM / 2;               // 4608 (2 lines/block)
    const int slideBlocks = (DIM * DIM * 16) / 256;      // 576

    binx_kernel<<<binBlocks, 256>>>(x, (__half*)p0);                         // x -> Xsum(h0)
    slideY_kernel<<<slideBlocks, 256>>>((const uint2*)p0, (uint2*)p1);       // h0 -> h1
    slideZ_kernel<<<slideBlocks, 256>>>((const uint2*)p1, (float4*)d_out);   // h1 -> out
}

// round 15
// speedup vs baseline: 1.9711x; 1.1083x over previous
#include <cuda_runtime.h>
#include <cuda_fp16.h>

// Problem constants
#define DIM   96
#define NBIN  64              // 8 theta * 8 phi
#define BSZ   15              // sliding window
#define NVOX  (DIM*DIM*DIM)               // 884736
#define NFLT  ((size_t)NVOX * NBIN)       // 56,623,104
#define LINEH2 (DIM * NBIN / 2)           // half2 per (z,y) line = 3072
#define LINEU2  (DIM * NBIN / 4)          // uint2 per y-row = 1536
#define PLANEU2 (DIM * LINEU2)            // 147456
#define VSTR2 33                          // half2 per x-row in smem (odd -> conflict-free)

// ONE 113 MB fp16 scratch buffer — fits in L2 (126 MB). slideY runs in place.
__device__ __align__(16) __half g_h0[NFLT];

__device__ __forceinline__ unsigned pack2(float a, float b) {
    __half2 h = __float22half2_rn(make_float2(a, b));
    return *reinterpret_cast<unsigned*>(&h);
}
__device__ __forceinline__ float2 unpack2(unsigned u) {
    __half2 h = *reinterpret_cast<__half2*>(&u);
    return __half22float2(h);
}

// ---------------------------------------------------------------------------
// Stage 1: gradients -> soft binning (fp16 smem) -> X sliding sum (half2) -> fp16
// One block (256 thr) per TWO (z,y) lines. Default stores -> L2 resident.
// ---------------------------------------------------------------------------
__global__ void __launch_bounds__(256) binx_kernel(const float* __restrict__ x,
                                                   __half* __restrict__ V)
{
    __shared__ __align__(16) __half2 Vs2[2 * DIM * VSTR2];   // 24.75 KB

    const int tid   = threadIdx.x;
    const int line0 = blockIdx.x * 2;

    {
        uint4* z4 = reinterpret_cast<uint4*>(Vs2);
        const uint4 zz = make_uint4(0u, 0u, 0u, 0u);
        #pragma unroll
        for (int i = tid; i < 2 * DIM * VSTR2 / 4; i += 256) z4[i] = zz;
    }
    __syncthreads();

    if (tid < 2 * DIM) {
        const int l    = tid / DIM;
        const int xi   = tid % DIM;
        const int line = line0 + l;
        const int yi   = line % DIM;
        const int zi   = line / DIM;
        const int v    = (zi * DIM + yi) * DIM + xi;

        const float xp = (xi < DIM - 1) ? x[v + 1]       : 0.f;
        const float xm = (xi > 0)       ? x[v - 1]       : 0.f;
        const float yp = (yi < DIM - 1) ? x[v + DIM]     : 0.f;
        const float ym = (yi > 0)       ? x[v - DIM]     : 0.f;
        const float zp = (zi < DIM - 1) ? x[v + DIM*DIM] : 0.f;
        const float zm = (zi > 0)       ? x[v - DIM*DIM] : 0.f;
        const float gx = xp - xm, gy = yp - ym, gz = zp - zm;

        const float EPS    = 2.2204460492503131e-16f;
        const float TWO_PI = (float)(2.0 * 3.14159265358979323846);
        const float PI_F   = (float)(3.14159265358979323846);
        const float TSTEP  = TWO_PI / 8.0f;
        const float PSTEP  = PI_F   / 8.0f;

        const float r   = sqrtf(gx*gx + gy*gy + gz*gz);
        float theta     = atanf(gy / (gx + EPS));
        const float phi = acosf(gz / (r + EPS));
        if (theta < 0.f) theta += TWO_PI;

        const float t_raw = theta / TSTEP;
        const float p_raw = phi   / PSTEP;

        const float ft = floorf(t_raw);
        int lt = (int)ft;            if (lt == 8) lt = 0;
        int lp = (int)floorf(p_raw); if (lp == 8) lp = 0;
        const int ht = (lt + 1) & 7;
        const int hp = (lp + 1) & 7;

        // theta frac intentionally reused for phi ratios (reference bug, faithful)
        const float frac  = t_raw - ft;
        const float w_lo  = fminf(frac, 1.0f - frac);
        const float w_hi  = 1.0f - w_lo;
        const float wp_lo = (frac == 0.0f) ? 1.0f : w_lo;
        const float wp_hi = 1.0f - wp_lo;

        // 4 target bins are provably distinct -> plain fp16 stores
        __half* row = reinterpret_cast<__half*>(Vs2) + (l * DIM + xi) * (2 * VSTR2);
        row[lt*8 + lp] = __float2half_rn(r * w_lo * wp_lo);
        row[ht*8 + lp] = __float2half_rn(r * w_hi * wp_lo);
        row[lt*8 + hp] = __float2half_rn(r * w_lo * wp_hi);
        row[ht*8 + hp] = __float2half_rn(r * w_hi * wp_hi);
    }
    __syncthreads();

    // running X-window in half2: thread = (line l, bin-word b, segment of 24 x)
    {
        const int l   = tid >> 7;
        const int u   = tid & 127;
        const int b   = u & 31;
        const int seg = u >> 5;
        const int i0  = seg * 24;

        const __half2* row = Vs2 + l * (DIM * VSTR2);

        __half2 w = __float2half2_rn(0.f);
        #pragma unroll
        for (int j = 0; j < BSZ - 1; j++) {
            w = __hadd2(w, row[(i0 + j) * VSTR2 + b]);
        }

        __half2* outv = reinterpret_cast<__half2*>(V) + (size_t)(line0 + l) * LINEH2;
        #pragma unroll
        for (int i = i0; i < i0 + 24; i++) {
            const int hi = i + BSZ - 1;
            if (hi < DIM) w = __hadd2(w, row[hi * VSTR2 + b]);
            outv[i * 32 + b] = w;                 // default store: keep in L2
            w = __hsub2(w, row[i * VSTR2 + b]);
        }
    }
}

// ---------------------------------------------------------------------------
// Stage 2: sliding sum along Y, fp16 -> fp16, IN PLACE on g_h0.
// Each thread owns a whole (z,x,q) column; at step i it reads the trailing
// element (old value) BEFORE overwriting the same address, so all reads see
// pre-pass data. Default loads/stores keep the buffer L2-resident.
// ---------------------------------------------------------------------------
__global__ void __launch_bounds__(256) slideY_kernel(uint2* __restrict__ buf)
{
    const int t = blockIdx.x * 256 + threadIdx.x;   // < 96*96*16 (grid exact)
    const int q = t & 15;
    const int c = t >> 4;
    const int xi = c % DIM, zi = c / DIM;
    const int base   = zi * PLANEU2 + xi * 16 + q;
    const int stride = LINEU2;

    float s0 = 0.f, s1 = 0.f, s2 = 0.f, s3 = 0.f;
    #pragma unroll
    for (int j = 0; j < BSZ - 1; j++) {
        const uint2 u = buf[base + j * stride];
        const float2 a = unpack2(u.x), b = unpack2(u.y);
        s0 += a.x; s1 += a.y; s2 += b.x; s3 += b.y;
    }

    int off = base;
    #pragma unroll 4
    for (int i = 0; i < DIM; i++) {
        if (i + BSZ - 1 < DIM) {
            const uint2 u = buf[base + (i + BSZ - 1) * stride];
            const float2 a = unpack2(u.x), b = unpack2(u.y);
            s0 += a.x; s1 += a.y; s2 += b.x; s3 += b.y;
        }
        // read trailing (old) BEFORE overwriting the same address
        const uint2 u = buf[off];
        const float2 a = unpack2(u.x), b = unpack2(u.y);
        uint2 o; o.x = pack2(s0, s1); o.y = pack2(s2, s3);
        buf[off] = o;                                // in-place, stays in L2
        s0 -= a.x; s1 -= a.y; s2 -= b.x; s3 -= b.y;
        off += stride;
    }
}

// ---------------------------------------------------------------------------
// Stage 3: sliding sum along Z, fp16 (L2-resident) -> fp32 d_out (streaming).
// ---------------------------------------------------------------------------
__global__ void __launch_bounds__(256) slideZ_kernel(const uint2* __restrict__ in,
                                                     float4* __restrict__ out)
{
    const int t = blockIdx.x * 256 + threadIdx.x;   // < 96*96*16
    const int q = t & 15;
    const int c = t >> 4;
    const int xi = c % DIM, yi = c / DIM;
    const int base   = yi * LINEU2 + xi * 16 + q;
    const int stride = PLANEU2;

    float s0 = 0.f, s1 = 0.f, s2 = 0.f, s3 = 0.f;
    #pragma unroll
    for (int j = 0; j < BSZ - 1; j++) {
        const uint2 u = in[base + j * stride];
        const float2 a = unpack2(u.x), b = unpack2(u.y);
        s0 += a.x; s1 += a.y; s2 += b.x; s3 += b.y;
    }

    int off = base;
    #pragma unroll 4
    for (int i = 0; i < DIM; i++) {
        if (i + BSZ - 1 < DIM) {
            const uint2 u = in[base + (i + BSZ - 1) * stride];
            const float2 a = unpack2(u.x), b = unpack2(u.y);
            s0 += a.x; s1 += a.y; s2 += b.x; s3 += b.y;
        }
        __stcs(&out[((i * DIM + yi) * DIM + xi) * 16 + q],
               make_float4(s0, s1, s2, s3));        // streaming: don't evict h0
        const uint2 u = in[off];                    // trailing (L2 hit)
        const float2 a = unpack2(u.x), b = unpack2(u.y);
        s0 -= a.x; s1 -= a.y; s2 -= b.x; s3 -= b.y;
        off += stride;
    }
}

// ---------------------------------------------------------------------------
extern "C" void kernel_launch(void* const* d_in, const int* in_sizes, int n_in,
                              void* d_out, int out_size)
{
    const float* x = (const float*)d_in[0];

    void* p0 = nullptr;
    cudaGetSymbolAddress(&p0, g_h0);

    const int binBlocks   = DIM * DIM / 2;               // 4608 (2 lines/block)
    const int slideBlocks = (DIM * DIM * 16) / 256;      // 576

    binx_kernel<<<binBlocks, 256>>>(x, (__half*)p0);                        // x -> Xsum(h0)
    slideY_kernel<<<slideBlocks, 256>>>((uint2*)p0);                        // h0 in-place
    slideZ_kernel<<<slideBlocks, 256>>>((const uint2*)p0, (float4*)d_out);  // h0 -> out
}